// round 7
// baseline (speedup 1.0000x reference)
#include <cuda_runtime.h>
#include <cuda_fp16.h>
#include <cstdint>

// ----------------------------------------------------------------------------
// LatentReasoningModule, sm_100 legacy tensor-core path.
//   fp16 mma.m16n8k16 (fp32 accum), ldmatrix, cp.async.
//   encode: H(2048)->2L(1024) relu ->L(512)
//   8x GRU(512): fused GEMM+gate kernel. R7: CTA 256x96, warp tile 64x48,
//                4-stage pipeline, 1 CTA/SM (cuts LDSM traffic 30%).
//   decode: L->2L relu ->H
// ----------------------------------------------------------------------------

#define MROWS 8192
#define THREADS 256
#define SROW 144                    // bytes per smem row: 64 halves + 8 pad

// ---- main GEMM tile (encode/decode): 3-stage (unchanged from R6) ----
#define BM 128
#define BN 128
#define BK 64
#define AB_BYTES   (BM * SROW)          // 18432
#define STG_BYTES  (2 * AB_BYTES)       // 36864
#define SMEM_MAIN  (3 * STG_BYTES)      // 110592

// ---- GRU GEMM tile: BM=256, BN=96, warp tile 64x48, 4-stage ----
#define GBM 256
#define GBN 96
#define GSTG ((GBM + GBN) * SROW)       // 50688
#define SMEM_GRU (4 * GSTG)             // 202752

// ---------------- scratch (device globals) ------------------------------------
__device__ __half g_xh[(size_t)MROWS * 2048];
__device__ __half g_h1h[(size_t)MROWS * 1024];
__device__ __half g_lath[2][(size_t)MROWS * 512];
__device__ float  g_latf[2][(size_t)MROWS * 512];
#define OFF_ENC1  0
#define OFF_ENC2  2097152
#define OFF_DEC1  2621440
#define OFF_DEC2  3145728
__device__ __half g_wh[5242880];
__device__ __half g_wgru[3072 * 512];   // gate-grouped GRU weights (8-dim groups)

// ---------------- helpers -----------------------------------------------------
__device__ __forceinline__ uint32_t smem_u32(const void* p) {
    uint32_t a;
    asm("{ .reg .u64 t; cvta.to.shared.u64 t, %1; cvt.u32.u64 %0, t; }"
        : "=r"(a) : "l"(p));
    return a;
}
__device__ __forceinline__ void cp16(uint32_t dst, const void* src) {
    asm volatile("cp.async.cg.shared.global [%0], [%1], 16;"
                 :: "r"(dst), "l"(src));
}
__device__ __forceinline__ void cp_commit() {
    asm volatile("cp.async.commit_group;" ::: "memory");
}
template <int N>
__device__ __forceinline__ void cp_wait() {
    asm volatile("cp.async.wait_group %0;" :: "n"(N) : "memory");
}
__device__ __forceinline__ void ldsm4(uint32_t* r, uint32_t addr) {
    asm volatile("ldmatrix.sync.aligned.m8n8.x4.shared.b16 {%0,%1,%2,%3}, [%4];"
                 : "=r"(r[0]), "=r"(r[1]), "=r"(r[2]), "=r"(r[3]) : "r"(addr));
}
__device__ __forceinline__ void mma16(float* c, const uint32_t* a, const uint32_t* b) {
    asm volatile(
        "mma.sync.aligned.m16n8k16.row.col.f32.f16.f16.f32 "
        "{%0,%1,%2,%3},{%4,%5,%6,%7},{%8,%9},{%0,%1,%2,%3};"
        : "+f"(c[0]), "+f"(c[1]), "+f"(c[2]), "+f"(c[3])
        : "r"(a[0]), "r"(a[1]), "r"(a[2]), "r"(a[3]), "r"(b[0]), "r"(b[1]));
}
__device__ __forceinline__ float sigmf(float x) {
    return 1.f / (1.f + __expf(-x));
}

// ---------------- main fp16 GEMM (encode/decode) -------------------------------
__global__ __launch_bounds__(THREADS, 2) void gemm_f16(
    const __half* __restrict__ A, int lda,
    const __half* __restrict__ B, int ldb,
    const float* __restrict__ bias,
    float* __restrict__ Cf, __half* __restrict__ Ch, int ldc,
    int K, int do_relu)
{
    extern __shared__ __align__(16) char sm[];
    const uint32_t sbase = smem_u32(sm);

    const int tid  = threadIdx.x;
    const int warp = tid >> 5;
    const int lane = tid & 31;
    const int bm = blockIdx.y * BM;
    const int bn = blockIdx.x * BN;
    const int wm = (warp & 3) * 32;
    const int wn = (warp >> 2) * 64;
    const int grp = lane >> 2;
    const int qid = lane & 3;
    const int arow = ((lane >> 3) & 1) * 8 + (lane & 7);
    const int acol = ((lane >> 4) & 1) * 8;
    const int brow = ((lane >> 4) & 1) * 8 + (lane & 7);
    const int bcol = ((lane >> 3) & 1) * 8;

    float acc[2][8][4];
#pragma unroll
    for (int i = 0; i < 2; i++)
#pragma unroll
        for (int j = 0; j < 8; j++)
#pragma unroll
            for (int k = 0; k < 4; k++) acc[i][j][k] = 0.f;

    const int niter = K / BK;

    auto load_tile = [&](int it) {
        const int k0 = it * BK;
        const uint32_t sa = sbase + (uint32_t)(it % 3) * STG_BYTES;
        const uint32_t sb = sa + AB_BYTES;
#pragma unroll
        for (int t = tid; t < 1024; t += THREADS) {
            int r = t >> 3, c = t & 7;
            cp16(sa + r * SROW + c * 16, A + (size_t)(bm + r) * lda + k0 + c * 8);
        }
#pragma unroll
        for (int t = tid; t < 1024; t += THREADS) {
            int r = t >> 3, c = t & 7;
            cp16(sb + r * SROW + c * 16, B + (size_t)(bn + r) * ldb + k0 + c * 8);
        }
        cp_commit();
    };

    load_tile(0);
    load_tile(1);

    for (int it = 0; it < niter; it++) {
        if (it + 1 < niter) cp_wait<1>(); else cp_wait<0>();
        __syncthreads();
        if (it + 2 < niter) load_tile(it + 2);

        const uint32_t sa = sbase + (uint32_t)(it % 3) * STG_BYTES;
        const uint32_t sb = sa + AB_BYTES;

#pragma unroll
        for (int kk = 0; kk < BK; kk += 16) {
            uint32_t af[2][4], bf[8][2];
#pragma unroll
            for (int mt = 0; mt < 2; mt++)
                ldsm4(af[mt], sa + (wm + mt * 16 + arow) * SROW + (kk + acol) * 2);
#pragma unroll
            for (int np = 0; np < 4; np++) {
                uint32_t r[4];
                ldsm4(r, sb + (wn + np * 16 + brow) * SROW + (kk + bcol) * 2);
                bf[2 * np][0] = r[0]; bf[2 * np][1] = r[1];
                bf[2 * np + 1][0] = r[2]; bf[2 * np + 1][1] = r[3];
            }
#pragma unroll
            for (int mt = 0; mt < 2; mt++)
#pragma unroll
                for (int nt = 0; nt < 8; nt++)
                    mma16(acc[mt][nt], af[mt], bf[nt]);
        }
    }

#pragma unroll
    for (int mt = 0; mt < 2; mt++) {
#pragma unroll
        for (int nt = 0; nt < 8; nt++) {
            int colN = bn + wn + nt * 8 + qid * 2;
            int row  = bm + wm + mt * 16 + grp;
            float2 bv = *(const float2*)(bias + colN);
            float2 v0, v1;
            v0.x = acc[mt][nt][0] + bv.x; v0.y = acc[mt][nt][1] + bv.y;
            v1.x = acc[mt][nt][2] + bv.x; v1.y = acc[mt][nt][3] + bv.y;
            if (do_relu) {
                v0.x = fmaxf(v0.x, 0.f); v0.y = fmaxf(v0.y, 0.f);
                v1.x = fmaxf(v1.x, 0.f); v1.y = fmaxf(v1.y, 0.f);
            }
            if (Cf) {
                *(float2*)(Cf + (size_t)row * ldc + colN)       = v0;
                *(float2*)(Cf + (size_t)(row + 8) * ldc + colN) = v1;
            }
            if (Ch) {
                *(__half2*)(Ch + (size_t)row * ldc + colN)       = __floats2half2_rn(v0.x, v0.y);
                *(__half2*)(Ch + (size_t)(row + 8) * ldc + colN) = __floats2half2_rn(v1.x, v1.y);
            }
        }
    }
}

// ---------------- fused GRU step (R7: 256x96 CTA, 64x48 warp tile) --------------
// Warp layout: wm = (warp&3)*64 (4 M-groups), wn = (warp>>2)*48 (2 gate groups).
// Each thread owns all 6 gate pre-acts for dims qid*2, qid*2+1 across 8 rows.
__global__ __launch_bounds__(THREADS, 1) void gemm_gru(
    const __half* __restrict__ A,
    const float* __restrict__ b_ih, const float* __restrict__ b_hh,
    const float* __restrict__ latf_in,
    float* __restrict__ latf_out, __half* __restrict__ lath_out,
    float* __restrict__ traj, int step)
{
    extern __shared__ __align__(16) char sm[];
    const uint32_t sbase = smem_u32(sm);

    const int tid  = threadIdx.x;
    const int warp = tid >> 5;
    const int lane = tid & 31;
    const int bm  = blockIdx.y * GBM;
    const int blk = blockIdx.x;               // 16-dim block, 0..31
    const int wm = (warp & 3) * 64;
    const int wn = (warp >> 2) * 48;          // 0 or 48
    const int grp = lane >> 2;
    const int qid = lane & 3;
    const int arow = ((lane >> 3) & 1) * 8 + (lane & 7);
    const int acol = ((lane >> 4) & 1) * 8;
    const int brow = ((lane >> 4) & 1) * 8 + (lane & 7);
    const int bcol = ((lane >> 3) & 1) * 8;

    const __half* Bw = g_wgru + (size_t)blk * GBN * 512;

    float acc[4][6][4];
#pragma unroll
    for (int i = 0; i < 4; i++)
#pragma unroll
        for (int j = 0; j < 6; j++)
#pragma unroll
            for (int k = 0; k < 4; k++) acc[i][j][k] = 0.f;

    const int niter = 512 / BK;               // 8

    auto load_tile = [&](int it) {
        const int k0 = it * BK;
        const uint32_t sa = sbase + (uint32_t)(it & 3) * GSTG;
        const uint32_t sb = sa + GBM * SROW;
#pragma unroll
        for (int t = tid; t < 2048; t += THREADS) {     // A: 256 rows x 8 chunks
            int r = t >> 3, c = t & 7;
            cp16(sa + r * SROW + c * 16, A + (size_t)(bm + r) * 512 + k0 + c * 8);
        }
#pragma unroll
        for (int t = tid; t < 768; t += THREADS) {      // B: 96 rows x 8 chunks
            int r = t >> 3, c = t & 7;
            cp16(sb + r * SROW + c * 16, Bw + (size_t)r * 512 + k0 + c * 8);
        }
        cp_commit();
    };

    load_tile(0);
    load_tile(1);
    load_tile(2);

    for (int it = 0; it < niter; it++) {
        if (it + 1 >= niter)      cp_wait<0>();
        else if (it + 2 >= niter) cp_wait<1>();
        else                      cp_wait<2>();
        __syncthreads();
        if (it + 3 < niter) load_tile(it + 3);

        const uint32_t sa = sbase + (uint32_t)(it & 3) * GSTG;
        const uint32_t sb = sa + GBM * SROW;

#pragma unroll
        for (int kk = 0; kk < BK; kk += 16) {
            uint32_t af[4][4], bf[6][2];
#pragma unroll
            for (int mt = 0; mt < 4; mt++)
                ldsm4(af[mt], sa + (wm + mt * 16 + arow) * SROW + (kk + acol) * 2);
#pragma unroll
            for (int np = 0; np < 3; np++) {
                uint32_t r[4];
                ldsm4(r, sb + (wn + np * 16 + brow) * SROW + (kk + bcol) * 2);
                bf[2 * np][0] = r[0]; bf[2 * np][1] = r[1];
                bf[2 * np + 1][0] = r[2]; bf[2 * np + 1][1] = r[3];
            }
#pragma unroll
            for (int mt = 0; mt < 4; mt++)
#pragma unroll
                for (int nt = 0; nt < 6; nt++)
                    mma16(acc[mt][nt], af[mt], bf[nt]);
        }
    }

    // ---- register-local GRU gate epilogue ----
    const int c = blk * 16 + (wn / 48) * 8 + qid * 2;
    const float2 bir = *(const float2*)(b_ih + c);
    const float2 biz = *(const float2*)(b_ih + 512 + c);
    const float2 bin = *(const float2*)(b_ih + 1024 + c);
    const float2 bhr = *(const float2*)(b_hh + c);
    const float2 bhz = *(const float2*)(b_hh + 512 + c);
    const float2 bhn = *(const float2*)(b_hh + 1024 + c);

#pragma unroll
    for (int mt = 0; mt < 4; mt++) {
#pragma unroll
        for (int hv = 0; hv < 2; hv++) {
            const int row = bm + wm + mt * 16 + grp + hv * 8;
            const int k0 = hv * 2;
            const float2 hin = *(const float2*)(latf_in + (size_t)row * 512 + c);

            float r0 = sigmf(acc[mt][0][k0]     + bir.x + acc[mt][3][k0]     + bhr.x);
            float r1 = sigmf(acc[mt][0][k0 + 1] + bir.y + acc[mt][3][k0 + 1] + bhr.y);
            float z0 = sigmf(acc[mt][1][k0]     + biz.x + acc[mt][4][k0]     + bhz.x);
            float z1 = sigmf(acc[mt][1][k0 + 1] + biz.y + acc[mt][4][k0 + 1] + bhz.y);
            float n0 = tanhf(acc[mt][2][k0]     + bin.x + r0 * (acc[mt][5][k0]     + bhn.x));
            float n1 = tanhf(acc[mt][2][k0 + 1] + bin.y + r1 * (acc[mt][5][k0 + 1] + bhn.y));
            float o0 = (1.f - z0) * n0 + z0 * hin.x;
            float o1 = (1.f - z1) * n1 + z1 * hin.y;

            *(float2*)(latf_out + (size_t)row * 512 + c) = make_float2(o0, o1);
            *(__half2*)(lath_out + (size_t)row * 512 + c) = __floats2half2_rn(o0, o1);
            *(float2*)(traj + (size_t)row * 4096 + step * 512 + c) = make_float2(o0, o1);
        }
    }
}

// ---------------- mega prep kernel (single launch) ------------------------------
#define PQ_X    4194304                 // 8192*2048/4
#define PQ_E1   (PQ_X + 524288)
#define PQ_E2   (PQ_E1 + 131072)
#define PQ_D1   (PQ_E2 + 131072)
#define PQ_D2   (PQ_D1 + 524288)
#define PQ_GRU  (PQ_D2 + 393216)
__global__ __launch_bounds__(256) void prep(
    const float* __restrict__ x,
    const float* __restrict__ We1, const float* __restrict__ We2,
    const float* __restrict__ Wd1, const float* __restrict__ Wd2,
    const float* __restrict__ w_ih, const float* __restrict__ w_hh)
{
    int i = blockIdx.x * blockDim.x + threadIdx.x;
    if (i >= PQ_GRU) return;
    const float4* src;
    __half2* dst;
    if (i < PQ_X) {
        src = (const float4*)x + i;
        dst = (__half2*)g_xh + 2 * (size_t)i;
    } else if (i < PQ_E1) {
        int j = i - PQ_X;
        src = (const float4*)We1 + j;
        dst = (__half2*)(g_wh + OFF_ENC1) + 2 * (size_t)j;
    } else if (i < PQ_E2) {
        int j = i - PQ_E1;
        src = (const float4*)We2 + j;
        dst = (__half2*)(g_wh + OFF_ENC2) + 2 * (size_t)j;
    } else if (i < PQ_D1) {
        int j = i - PQ_E2;
        src = (const float4*)Wd1 + j;
        dst = (__half2*)(g_wh + OFF_DEC1) + 2 * (size_t)j;
    } else if (i < PQ_D2) {
        int j = i - PQ_D1;
        src = (const float4*)Wd2 + j;
        dst = (__half2*)(g_wh + OFF_DEC2) + 2 * (size_t)j;
    } else {
        int j = i - PQ_D2;                 // gru reorder: 3072 rows x 128 quads
        int o = j >> 7, q = j & 127;
        int d48 = o / 48, rem = o % 48, g = rem >> 3, e = rem & 7;
        int cc = d48 * 8 + e;
        const float* s = (g < 3) ? (w_ih + (size_t)(g * 512 + cc) * 512)
                                 : (w_hh + (size_t)((g - 3) * 512 + cc) * 512);
        src = (const float4*)s + q;
        dst = (__half2*)(g_wgru + (size_t)o * 512) + 2 * q;
    }
    float4 v = *src;
    dst[0] = __floats2half2_rn(v.x, v.y);
    dst[1] = __floats2half2_rn(v.z, v.w);
}

// ---------------- launch ---------------------------------------------------------
extern "C" void kernel_launch(void* const* d_in, const int* in_sizes, int n_in,
                              void* d_out, int out_size)
{
    const int bse = (n_in >= 14) ? 2 : 1;
    const float* x      = (const float*)d_in[0];
    const float* W_enc1 = (const float*)d_in[bse + 0];
    const float* b_enc1 = (const float*)d_in[bse + 1];
    const float* W_enc2 = (const float*)d_in[bse + 2];
    const float* b_enc2 = (const float*)d_in[bse + 3];
    const float* W_dec1 = (const float*)d_in[bse + 4];
    const float* b_dec1 = (const float*)d_in[bse + 5];
    const float* W_dec2 = (const float*)d_in[bse + 6];
    const float* b_dec2 = (const float*)d_in[bse + 7];
    const float* w_ih   = (const float*)d_in[bse + 8];
    const float* w_hh   = (const float*)d_in[bse + 9];
    const float* b_ih   = (const float*)d_in[bse + 10];
    const float* b_hh   = (const float*)d_in[bse + 11];

    float* decoded = (float*)d_out;
    float* traj    = decoded + (size_t)MROWS * 2048;

    __half *xh, *h1h, *wh;
    __half *lath[2];
    float *latf[2];
    cudaGetSymbolAddress((void**)&xh,  g_xh);
    cudaGetSymbolAddress((void**)&h1h, g_h1h);
    cudaGetSymbolAddress((void**)&wh,  g_wh);
    {   __half* p; cudaGetSymbolAddress((void**)&p, g_lath);
        lath[0] = p; lath[1] = p + (size_t)MROWS * 512; }
    {   float* p; cudaGetSymbolAddress((void**)&p, g_latf);
        latf[0] = p; latf[1] = p + (size_t)MROWS * 512; }

    cudaFuncSetAttribute(gemm_f16, cudaFuncAttributeMaxDynamicSharedMemorySize, SMEM_MAIN);
    cudaFuncSetAttribute(gemm_gru, cudaFuncAttributeMaxDynamicSharedMemorySize, SMEM_GRU);

    const dim3 blk(THREADS);
    const int gy = MROWS / BM;  // 64

    // launch 0: all prep work in one kernel
    prep<<<(PQ_GRU + 255) / 256, 256>>>(x, W_enc1, W_enc2, W_dec1, W_dec2,
                                        w_ih, w_hh);

    // launches 1,2: encode
    gemm_f16<<<dim3(1024 / BN, gy), blk, SMEM_MAIN>>>(
        xh, 2048, wh + OFF_ENC1, 2048, b_enc1, nullptr, h1h, 1024, 2048, 1);
    gemm_f16<<<dim3(512 / BN, gy), blk, SMEM_MAIN>>>(
        h1h, 1024, wh + OFF_ENC2, 1024, b_enc2, latf[0], lath[0], 512, 1024, 0);

    // launches 3..10: 8 fused GRU steps (launch #5 = step 2, for ncu -s 5)
    for (int step = 0; step < 8; step++) {
        int s = step & 1, t = s ^ 1;
        gemm_gru<<<dim3(32, MROWS / GBM), blk, SMEM_GRU>>>(
            lath[s], b_ih, b_hh, latf[s], latf[t], lath[t], traj, step);
    }

    // launches 11,12: decode
    gemm_f16<<<dim3(1024 / BN, gy), blk, SMEM_MAIN>>>(
        lath[0], 512, wh + OFF_DEC1, 512, b_dec1, nullptr, h1h, 1024, 512, 1);
    gemm_f16<<<dim3(2048 / BN, gy), blk, SMEM_MAIN>>>(
        h1h, 1024, wh + OFF_DEC2, 1024, b_dec2, decoded, nullptr, 2048, 1024, 0);
}

// round 8
// speedup vs baseline: 1.0523x; 1.0523x over previous
#include <cuda_runtime.h>
#include <cuda_fp16.h>
#include <cstdint>

// ----------------------------------------------------------------------------
// LatentReasoningModule, sm_100 legacy tensor-core path.
//   fp16 mma.m16n8k16 (fp32 accum), ldmatrix, cp.async, 1 sync/k-tile.
//   encode: H(2048)->2L(1024) relu ->L(512)
//   8x GRU(512): fused GEMM+gate kernel. R8: CTA 128x96 with 4 warps
//                (warp tile 64x48), 3-stage, 2 CTAs/SM -> 30% less LDSM
//                traffic than R6 while keeping two independent CTAs per SM.
//   decode: L->2L relu ->H
// ----------------------------------------------------------------------------

#define MROWS 8192
#define THREADS 256
#define GTHREADS 128                // GRU CTA threads (4 warps)
#define SROW 144                    // bytes per smem row: 64 halves + 8 pad

// ---- main GEMM tile (encode/decode): 3-stage (unchanged from R6) ----
#define BM 128
#define BN 128
#define BK 64
#define AB_BYTES   (BM * SROW)          // 18432
#define STG_BYTES  (2 * AB_BYTES)       // 36864
#define SMEM_MAIN  (3 * STG_BYTES)      // 110592

// ---- GRU GEMM tile: CTA 128x96, warp tile 64x48, 3-stage ----
#define GBN 96
#define GSTG ((BM + GBN) * SROW)        // 32256
#define SMEM_GRU (3 * GSTG)             // 96768  (x2 CTAs = 193.5 KB/SM)

// ---------------- scratch (device globals) ------------------------------------
__device__ __half g_xh[(size_t)MROWS * 2048];
__device__ __half g_h1h[(size_t)MROWS * 1024];
__device__ __half g_lath[2][(size_t)MROWS * 512];
__device__ float  g_latf[2][(size_t)MROWS * 512];
#define OFF_ENC1  0
#define OFF_ENC2  2097152
#define OFF_DEC1  2621440
#define OFF_DEC2  3145728
__device__ __half g_wh[5242880];
__device__ __half g_wgru[3072 * 512];   // gate-grouped GRU weights (8-dim groups)

// ---------------- helpers -----------------------------------------------------
__device__ __forceinline__ uint32_t smem_u32(const void* p) {
    uint32_t a;
    asm("{ .reg .u64 t; cvta.to.shared.u64 t, %1; cvt.u32.u64 %0, t; }"
        : "=r"(a) : "l"(p));
    return a;
}
__device__ __forceinline__ void cp16(uint32_t dst, const void* src) {
    asm volatile("cp.async.cg.shared.global [%0], [%1], 16;"
                 :: "r"(dst), "l"(src));
}
__device__ __forceinline__ void cp_commit() {
    asm volatile("cp.async.commit_group;" ::: "memory");
}
template <int N>
__device__ __forceinline__ void cp_wait() {
    asm volatile("cp.async.wait_group %0;" :: "n"(N) : "memory");
}
__device__ __forceinline__ void ldsm4(uint32_t* r, uint32_t addr) {
    asm volatile("ldmatrix.sync.aligned.m8n8.x4.shared.b16 {%0,%1,%2,%3}, [%4];"
                 : "=r"(r[0]), "=r"(r[1]), "=r"(r[2]), "=r"(r[3]) : "r"(addr));
}
__device__ __forceinline__ void mma16(float* c, const uint32_t* a, const uint32_t* b) {
    asm volatile(
        "mma.sync.aligned.m16n8k16.row.col.f32.f16.f16.f32 "
        "{%0,%1,%2,%3},{%4,%5,%6,%7},{%8,%9},{%0,%1,%2,%3};"
        : "+f"(c[0]), "+f"(c[1]), "+f"(c[2]), "+f"(c[3])
        : "r"(a[0]), "r"(a[1]), "r"(a[2]), "r"(a[3]), "r"(b[0]), "r"(b[1]));
}
__device__ __forceinline__ float sigmf(float x) {
    return 1.f / (1.f + __expf(-x));
}

// ---------------- main fp16 GEMM (encode/decode) -------------------------------
__global__ __launch_bounds__(THREADS, 2) void gemm_f16(
    const __half* __restrict__ A, int lda,
    const __half* __restrict__ B, int ldb,
    const float* __restrict__ bias,
    float* __restrict__ Cf, __half* __restrict__ Ch, int ldc,
    int K, int do_relu)
{
    extern __shared__ __align__(16) char sm[];
    const uint32_t sbase = smem_u32(sm);

    const int tid  = threadIdx.x;
    const int warp = tid >> 5;
    const int lane = tid & 31;
    const int bm = blockIdx.y * BM;
    const int bn = blockIdx.x * BN;
    const int wm = (warp & 3) * 32;
    const int wn = (warp >> 2) * 64;
    const int grp = lane >> 2;
    const int qid = lane & 3;
    const int arow = ((lane >> 3) & 1) * 8 + (lane & 7);
    const int acol = ((lane >> 4) & 1) * 8;
    const int brow = ((lane >> 4) & 1) * 8 + (lane & 7);
    const int bcol = ((lane >> 3) & 1) * 8;

    float acc[2][8][4];
#pragma unroll
    for (int i = 0; i < 2; i++)
#pragma unroll
        for (int j = 0; j < 8; j++)
#pragma unroll
            for (int k = 0; k < 4; k++) acc[i][j][k] = 0.f;

    const int niter = K / BK;

    auto load_tile = [&](int it) {
        const int k0 = it * BK;
        const uint32_t sa = sbase + (uint32_t)(it % 3) * STG_BYTES;
        const uint32_t sb = sa + AB_BYTES;
#pragma unroll
        for (int t = tid; t < 1024; t += THREADS) {
            int r = t >> 3, c = t & 7;
            cp16(sa + r * SROW + c * 16, A + (size_t)(bm + r) * lda + k0 + c * 8);
        }
#pragma unroll
        for (int t = tid; t < 1024; t += THREADS) {
            int r = t >> 3, c = t & 7;
            cp16(sb + r * SROW + c * 16, B + (size_t)(bn + r) * ldb + k0 + c * 8);
        }
        cp_commit();
    };

    load_tile(0);
    load_tile(1);

    for (int it = 0; it < niter; it++) {
        if (it + 1 < niter) cp_wait<1>(); else cp_wait<0>();
        __syncthreads();
        if (it + 2 < niter) load_tile(it + 2);

        const uint32_t sa = sbase + (uint32_t)(it % 3) * STG_BYTES;
        const uint32_t sb = sa + AB_BYTES;

#pragma unroll
        for (int kk = 0; kk < BK; kk += 16) {
            uint32_t af[2][4], bf[8][2];
#pragma unroll
            for (int mt = 0; mt < 2; mt++)
                ldsm4(af[mt], sa + (wm + mt * 16 + arow) * SROW + (kk + acol) * 2);
#pragma unroll
            for (int np = 0; np < 4; np++) {
                uint32_t r[4];
                ldsm4(r, sb + (wn + np * 16 + brow) * SROW + (kk + bcol) * 2);
                bf[2 * np][0] = r[0]; bf[2 * np][1] = r[1];
                bf[2 * np + 1][0] = r[2]; bf[2 * np + 1][1] = r[3];
            }
#pragma unroll
            for (int mt = 0; mt < 2; mt++)
#pragma unroll
                for (int nt = 0; nt < 8; nt++)
                    mma16(acc[mt][nt], af[mt], bf[nt]);
        }
    }

#pragma unroll
    for (int mt = 0; mt < 2; mt++) {
#pragma unroll
        for (int nt = 0; nt < 8; nt++) {
            int colN = bn + wn + nt * 8 + qid * 2;
            int row  = bm + wm + mt * 16 + grp;
            float2 bv = *(const float2*)(bias + colN);
            float2 v0, v1;
            v0.x = acc[mt][nt][0] + bv.x; v0.y = acc[mt][nt][1] + bv.y;
            v1.x = acc[mt][nt][2] + bv.x; v1.y = acc[mt][nt][3] + bv.y;
            if (do_relu) {
                v0.x = fmaxf(v0.x, 0.f); v0.y = fmaxf(v0.y, 0.f);
                v1.x = fmaxf(v1.x, 0.f); v1.y = fmaxf(v1.y, 0.f);
            }
            if (Cf) {
                *(float2*)(Cf + (size_t)row * ldc + colN)       = v0;
                *(float2*)(Cf + (size_t)(row + 8) * ldc + colN) = v1;
            }
            if (Ch) {
                *(__half2*)(Ch + (size_t)row * ldc + colN)       = __floats2half2_rn(v0.x, v0.y);
                *(__half2*)(Ch + (size_t)(row + 8) * ldc + colN) = __floats2half2_rn(v1.x, v1.y);
            }
        }
    }
}

// ---------------- fused GRU step (R8: 128x96 CTA, 4 warps, 64x48 warp tile) -----
// warp 0..3: wm = (warp&1)*64, wn = (warp>>1)*48.
// Each thread owns all 6 gate pre-acts for dims qid*2, qid*2+1 across 16 rows.
__global__ __launch_bounds__(GTHREADS, 2) void gemm_gru(
    const __half* __restrict__ A,
    const float* __restrict__ b_ih, const float* __restrict__ b_hh,
    const float* __restrict__ latf_in,
    float* __restrict__ latf_out, __half* __restrict__ lath_out,
    float* __restrict__ traj, int step)
{
    extern __shared__ __align__(16) char sm[];
    const uint32_t sbase = smem_u32(sm);

    const int tid  = threadIdx.x;
    const int warp = tid >> 5;
    const int lane = tid & 31;
    const int bm  = blockIdx.y * BM;
    const int blk = blockIdx.x;               // 16-dim block, 0..31
    const int wm = (warp & 1) * 64;
    const int wn = (warp >> 1) * 48;          // 0 or 48
    const int grp = lane >> 2;
    const int qid = lane & 3;
    const int arow = ((lane >> 3) & 1) * 8 + (lane & 7);
    const int acol = ((lane >> 4) & 1) * 8;
    const int brow = ((lane >> 4) & 1) * 8 + (lane & 7);
    const int bcol = ((lane >> 3) & 1) * 8;

    const __half* Bw = g_wgru + (size_t)blk * GBN * 512;

    float acc[4][6][4];
#pragma unroll
    for (int i = 0; i < 4; i++)
#pragma unroll
        for (int j = 0; j < 6; j++)
#pragma unroll
            for (int k = 0; k < 4; k++) acc[i][j][k] = 0.f;

    const int niter = 512 / BK;               // 8

    auto load_tile = [&](int it) {
        const int k0 = it * BK;
        const uint32_t sa = sbase + (uint32_t)(it % 3) * GSTG;
        const uint32_t sb = sa + BM * SROW;
#pragma unroll
        for (int t = tid; t < 1024; t += GTHREADS) {    // A: 128 rows x 8 chunks
            int r = t >> 3, c = t & 7;
            cp16(sa + r * SROW + c * 16, A + (size_t)(bm + r) * 512 + k0 + c * 8);
        }
#pragma unroll
        for (int t = tid; t < 768; t += GTHREADS) {     // B: 96 rows x 8 chunks
            int r = t >> 3, c = t & 7;
            cp16(sb + r * SROW + c * 16, Bw + (size_t)r * 512 + k0 + c * 8);
        }
        cp_commit();
    };

    load_tile(0);
    load_tile(1);

    for (int it = 0; it < niter; it++) {
        if (it + 1 < niter) cp_wait<1>(); else cp_wait<0>();
        __syncthreads();
        if (it + 2 < niter) load_tile(it + 2);

        const uint32_t sa = sbase + (uint32_t)(it % 3) * GSTG;
        const uint32_t sb = sa + BM * SROW;

#pragma unroll
        for (int kk = 0; kk < BK; kk += 16) {
            uint32_t af[4][4], bf[6][2];
#pragma unroll
            for (int mt = 0; mt < 4; mt++)
                ldsm4(af[mt], sa + (wm + mt * 16 + arow) * SROW + (kk + acol) * 2);
#pragma unroll
            for (int np = 0; np < 3; np++) {
                uint32_t r[4];
                ldsm4(r, sb + (wn + np * 16 + brow) * SROW + (kk + bcol) * 2);
                bf[2 * np][0] = r[0]; bf[2 * np][1] = r[1];
                bf[2 * np + 1][0] = r[2]; bf[2 * np + 1][1] = r[3];
            }
#pragma unroll
            for (int mt = 0; mt < 4; mt++)
#pragma unroll
                for (int nt = 0; nt < 6; nt++)
                    mma16(acc[mt][nt], af[mt], bf[nt]);
        }
    }

    // ---- register-local GRU gate epilogue ----
    const int c = blk * 16 + (wn / 48) * 8 + qid * 2;
    const float2 bir = *(const float2*)(b_ih + c);
    const float2 biz = *(const float2*)(b_ih + 512 + c);
    const float2 bin = *(const float2*)(b_ih + 1024 + c);
    const float2 bhr = *(const float2*)(b_hh + c);
    const float2 bhz = *(const float2*)(b_hh + 512 + c);
    const float2 bhn = *(const float2*)(b_hh + 1024 + c);

#pragma unroll
    for (int mt = 0; mt < 4; mt++) {
#pragma unroll
        for (int hv = 0; hv < 2; hv++) {
            const int row = bm + wm + mt * 16 + grp + hv * 8;
            const int k0 = hv * 2;
            const float2 hin = *(const float2*)(latf_in + (size_t)row * 512 + c);

            float r0 = sigmf(acc[mt][0][k0]     + bir.x + acc[mt][3][k0]     + bhr.x);
            float r1 = sigmf(acc[mt][0][k0 + 1] + bir.y + acc[mt][3][k0 + 1] + bhr.y);
            float z0 = sigmf(acc[mt][1][k0]     + biz.x + acc[mt][4][k0]     + bhz.x);
            float z1 = sigmf(acc[mt][1][k0 + 1] + biz.y + acc[mt][4][k0 + 1] + bhz.y);
            float n0 = tanhf(acc[mt][2][k0]     + bin.x + r0 * (acc[mt][5][k0]     + bhn.x));
            float n1 = tanhf(acc[mt][2][k0 + 1] + bin.y + r1 * (acc[mt][5][k0 + 1] + bhn.y));
            float o0 = (1.f - z0) * n0 + z0 * hin.x;
            float o1 = (1.f - z1) * n1 + z1 * hin.y;

            *(float2*)(latf_out + (size_t)row * 512 + c) = make_float2(o0, o1);
            *(__half2*)(lath_out + (size_t)row * 512 + c) = __floats2half2_rn(o0, o1);
            *(float2*)(traj + (size_t)row * 4096 + step * 512 + c) = make_float2(o0, o1);
        }
    }
}

// ---------------- mega prep kernel (single launch) ------------------------------
#define PQ_X    4194304                 // 8192*2048/4
#define PQ_E1   (PQ_X + 524288)
#define PQ_E2   (PQ_E1 + 131072)
#define PQ_D1   (PQ_E2 + 131072)
#define PQ_D2   (PQ_D1 + 524288)
#define PQ_GRU  (PQ_D2 + 393216)
__global__ __launch_bounds__(256) void prep(
    const float* __restrict__ x,
    const float* __restrict__ We1, const float* __restrict__ We2,
    const float* __restrict__ Wd1, const float* __restrict__ Wd2,
    const float* __restrict__ w_ih, const float* __restrict__ w_hh)
{
    int i = blockIdx.x * blockDim.x + threadIdx.x;
    if (i >= PQ_GRU) return;
    const float4* src;
    __half2* dst;
    if (i < PQ_X) {
        src = (const float4*)x + i;
        dst = (__half2*)g_xh + 2 * (size_t)i;
    } else if (i < PQ_E1) {
        int j = i - PQ_X;
        src = (const float4*)We1 + j;
        dst = (__half2*)(g_wh + OFF_ENC1) + 2 * (size_t)j;
    } else if (i < PQ_E2) {
        int j = i - PQ_E1;
        src = (const float4*)We2 + j;
        dst = (__half2*)(g_wh + OFF_ENC2) + 2 * (size_t)j;
    } else if (i < PQ_D1) {
        int j = i - PQ_E2;
        src = (const float4*)Wd1 + j;
        dst = (__half2*)(g_wh + OFF_DEC1) + 2 * (size_t)j;
    } else if (i < PQ_D2) {
        int j = i - PQ_D1;
        src = (const float4*)Wd2 + j;
        dst = (__half2*)(g_wh + OFF_DEC2) + 2 * (size_t)j;
    } else {
        int j = i - PQ_D2;                 // gru reorder: 3072 rows x 128 quads
        int o = j >> 7, q = j & 127;
        int d48 = o / 48, rem = o % 48, g = rem >> 3, e = rem & 7;
        int cc = d48 * 8 + e;
        const float* s = (g < 3) ? (w_ih + (size_t)(g * 512 + cc) * 512)
                                 : (w_hh + (size_t)((g - 3) * 512 + cc) * 512);
        src = (const float4*)s + q;
        dst = (__half2*)(g_wgru + (size_t)o * 512) + 2 * q;
    }
    float4 v = *src;
    dst[0] = __floats2half2_rn(v.x, v.y);
    dst[1] = __floats2half2_rn(v.z, v.w);
}

// ---------------- launch ---------------------------------------------------------
extern "C" void kernel_launch(void* const* d_in, const int* in_sizes, int n_in,
                              void* d_out, int out_size)
{
    const int bse = (n_in >= 14) ? 2 : 1;
    const float* x      = (const float*)d_in[0];
    const float* W_enc1 = (const float*)d_in[bse + 0];
    const float* b_enc1 = (const float*)d_in[bse + 1];
    const float* W_enc2 = (const float*)d_in[bse + 2];
    const float* b_enc2 = (const float*)d_in[bse + 3];
    const float* W_dec1 = (const float*)d_in[bse + 4];
    const float* b_dec1 = (const float*)d_in[bse + 5];
    const float* W_dec2 = (const float*)d_in[bse + 6];
    const float* b_dec2 = (const float*)d_in[bse + 7];
    const float* w_ih   = (const float*)d_in[bse + 8];
    const float* w_hh   = (const float*)d_in[bse + 9];
    const float* b_ih   = (const float*)d_in[bse + 10];
    const float* b_hh   = (const float*)d_in[bse + 11];

    float* decoded = (float*)d_out;
    float* traj    = decoded + (size_t)MROWS * 2048;

    __half *xh, *h1h, *wh;
    __half *lath[2];
    float *latf[2];
    cudaGetSymbolAddress((void**)&xh,  g_xh);
    cudaGetSymbolAddress((void**)&h1h, g_h1h);
    cudaGetSymbolAddress((void**)&wh,  g_wh);
    {   __half* p; cudaGetSymbolAddress((void**)&p, g_lath);
        lath[0] = p; lath[1] = p + (size_t)MROWS * 512; }
    {   float* p; cudaGetSymbolAddress((void**)&p, g_latf);
        latf[0] = p; latf[1] = p + (size_t)MROWS * 512; }

    cudaFuncSetAttribute(gemm_f16, cudaFuncAttributeMaxDynamicSharedMemorySize, SMEM_MAIN);
    cudaFuncSetAttribute(gemm_gru, cudaFuncAttributeMaxDynamicSharedMemorySize, SMEM_GRU);

    const dim3 blk(THREADS);
    const int gy = MROWS / BM;  // 64

    // launch 0: all prep work in one kernel
    prep<<<(PQ_GRU + 255) / 256, 256>>>(x, W_enc1, W_enc2, W_dec1, W_dec2,
                                        w_ih, w_hh);

    // launches 1,2: encode
    gemm_f16<<<dim3(1024 / BN, gy), blk, SMEM_MAIN>>>(
        xh, 2048, wh + OFF_ENC1, 2048, b_enc1, nullptr, h1h, 1024, 2048, 1);
    gemm_f16<<<dim3(512 / BN, gy), blk, SMEM_MAIN>>>(
        h1h, 1024, wh + OFF_ENC2, 1024, b_enc2, latf[0], lath[0], 512, 1024, 0);

    // launches 3..10: 8 fused GRU steps (launch #5 = step 2, for ncu -s 5)
    for (int step = 0; step < 8; step++) {
        int s = step & 1, t = s ^ 1;
        gemm_gru<<<dim3(32, MROWS / BM), dim3(GTHREADS), SMEM_GRU>>>(
            lath[s], b_ih, b_hh, latf[s], latf[t], lath[t], traj, step);
    }

    // launches 11,12: decode
    gemm_f16<<<dim3(1024 / BN, gy), blk, SMEM_MAIN>>>(
        lath[0], 512, wh + OFF_DEC1, 512, b_dec1, nullptr, h1h, 1024, 512, 1);
    gemm_f16<<<dim3(2048 / BN, gy), blk, SMEM_MAIN>>>(
        h1h, 1024, wh + OFF_DEC2, 1024, b_dec2, decoded, nullptr, 2048, 1024, 0);
}

// round 9
// speedup vs baseline: 1.2813x; 1.2176x over previous
#include <cuda_runtime.h>
#include <cuda_fp16.h>
#include <cstdint>

// ----------------------------------------------------------------------------
// LatentReasoningModule, sm_100 legacy tensor-core path.
//   fp16 mma.m16n8k16 (fp32 accum), ldmatrix, 3-stage cp.async, 1 sync/k-tile.
//   encode: H(2048)->2L(1024) relu ->L(512)
//   8x GRU(512): fused GEMM+gate kernel, R6 shape (CTA 128x96, 8 warps,
//                warp tile 32x48, 2 CTAs/SM). R9: h read from traj (latf
//                eliminated) + h prefetched to smem with k-tile 0.
//   decode: L->2L relu ->H
// ----------------------------------------------------------------------------

#define MROWS 8192
#define THREADS 256
#define SROW 144                    // bytes per smem row: 64 halves + 8 pad

// ---- main GEMM tile (encode/decode): 3-stage ----
#define BM 128
#define BN 128
#define BK 64
#define AB_BYTES   (BM * SROW)          // 18432
#define STG_BYTES  (2 * AB_BYTES)       // 36864
#define SMEM_MAIN  (3 * STG_BYTES)      // 110592

// ---- GRU GEMM tile: CTA 128x96, warp tile 32x48, 3-stage + h tile ----
#define GBN 96
#define GSTG ((BM + GBN) * SROW)        // 32256
#define HOFF (3 * GSTG)                 // 96768: h tile (128 rows x 16 f32)
#define SMEM_GRU (HOFF + BM * 64)       // 104960 (x2 CTAs = 205 KB/SM)

// ---------------- scratch (device globals) ------------------------------------
__device__ __half g_xh[(size_t)MROWS * 2048];
__device__ __half g_h1h[(size_t)MROWS * 1024];
__device__ __half g_lath[2][(size_t)MROWS * 512];
__device__ float  g_latf0[(size_t)MROWS * 512];   // encoder latent (h for step 0)
#define OFF_ENC1  0
#define OFF_ENC2  2097152
#define OFF_DEC1  2621440
#define OFF_DEC2  3145728
__device__ __half g_wh[5242880];
__device__ __half g_wgru[3072 * 512];   // gate-grouped GRU weights (8-dim groups)

// ---------------- helpers -----------------------------------------------------
__device__ __forceinline__ uint32_t smem_u32(const void* p) {
    uint32_t a;
    asm("{ .reg .u64 t; cvta.to.shared.u64 t, %1; cvt.u32.u64 %0, t; }"
        : "=r"(a) : "l"(p));
    return a;
}
__device__ __forceinline__ void cp16(uint32_t dst, const void* src) {
    asm volatile("cp.async.cg.shared.global [%0], [%1], 16;"
                 :: "r"(dst), "l"(src));
}
__device__ __forceinline__ void cp_commit() {
    asm volatile("cp.async.commit_group;" ::: "memory");
}
template <int N>
__device__ __forceinline__ void cp_wait() {
    asm volatile("cp.async.wait_group %0;" :: "n"(N) : "memory");
}
__device__ __forceinline__ void ldsm4(uint32_t* r, uint32_t addr) {
    asm volatile("ldmatrix.sync.aligned.m8n8.x4.shared.b16 {%0,%1,%2,%3}, [%4];"
                 : "=r"(r[0]), "=r"(r[1]), "=r"(r[2]), "=r"(r[3]) : "r"(addr));
}
__device__ __forceinline__ void mma16(float* c, const uint32_t* a, const uint32_t* b) {
    asm volatile(
        "mma.sync.aligned.m16n8k16.row.col.f32.f16.f16.f32 "
        "{%0,%1,%2,%3},{%4,%5,%6,%7},{%8,%9},{%0,%1,%2,%3};"
        : "+f"(c[0]), "+f"(c[1]), "+f"(c[2]), "+f"(c[3])
        : "r"(a[0]), "r"(a[1]), "r"(a[2]), "r"(a[3]), "r"(b[0]), "r"(b[1]));
}
__device__ __forceinline__ float sigmf(float x) {
    return 1.f / (1.f + __expf(-x));
}

// ---------------- main fp16 GEMM (encode/decode) -------------------------------
__global__ __launch_bounds__(THREADS, 2) void gemm_f16(
    const __half* __restrict__ A, int lda,
    const __half* __restrict__ B, int ldb,
    const float* __restrict__ bias,
    float* __restrict__ Cf, __half* __restrict__ Ch, int ldc,
    int K, int do_relu)
{
    extern __shared__ __align__(16) char sm[];
    const uint32_t sbase = smem_u32(sm);

    const int tid  = threadIdx.x;
    const int warp = tid >> 5;
    const int lane = tid & 31;
    const int bm = blockIdx.y * BM;
    const int bn = blockIdx.x * BN;
    const int wm = (warp & 3) * 32;
    const int wn = (warp >> 2) * 64;
    const int grp = lane >> 2;
    const int qid = lane & 3;
    const int arow = ((lane >> 3) & 1) * 8 + (lane & 7);
    const int acol = ((lane >> 4) & 1) * 8;
    const int brow = ((lane >> 4) & 1) * 8 + (lane & 7);
    const int bcol = ((lane >> 3) & 1) * 8;

    float acc[2][8][4];
#pragma unroll
    for (int i = 0; i < 2; i++)
#pragma unroll
        for (int j = 0; j < 8; j++)
#pragma unroll
            for (int k = 0; k < 4; k++) acc[i][j][k] = 0.f;

    const int niter = K / BK;

    auto load_tile = [&](int it) {
        const int k0 = it * BK;
        const uint32_t sa = sbase + (uint32_t)(it % 3) * STG_BYTES;
        const uint32_t sb = sa + AB_BYTES;
#pragma unroll
        for (int t = tid; t < 1024; t += THREADS) {
            int r = t >> 3, c = t & 7;
            cp16(sa + r * SROW + c * 16, A + (size_t)(bm + r) * lda + k0 + c * 8);
        }
#pragma unroll
        for (int t = tid; t < 1024; t += THREADS) {
            int r = t >> 3, c = t & 7;
            cp16(sb + r * SROW + c * 16, B + (size_t)(bn + r) * ldb + k0 + c * 8);
        }
        cp_commit();
    };

    load_tile(0);
    load_tile(1);

    for (int it = 0; it < niter; it++) {
        if (it + 1 < niter) cp_wait<1>(); else cp_wait<0>();
        __syncthreads();
        if (it + 2 < niter) load_tile(it + 2);

        const uint32_t sa = sbase + (uint32_t)(it % 3) * STG_BYTES;
        const uint32_t sb = sa + AB_BYTES;

#pragma unroll
        for (int kk = 0; kk < BK; kk += 16) {
            uint32_t af[2][4], bf[8][2];
#pragma unroll
            for (int mt = 0; mt < 2; mt++)
                ldsm4(af[mt], sa + (wm + mt * 16 + arow) * SROW + (kk + acol) * 2);
#pragma unroll
            for (int np = 0; np < 4; np++) {
                uint32_t r[4];
                ldsm4(r, sb + (wn + np * 16 + brow) * SROW + (kk + bcol) * 2);
                bf[2 * np][0] = r[0]; bf[2 * np][1] = r[1];
                bf[2 * np + 1][0] = r[2]; bf[2 * np + 1][1] = r[3];
            }
#pragma unroll
            for (int mt = 0; mt < 2; mt++)
#pragma unroll
                for (int nt = 0; nt < 8; nt++)
                    mma16(acc[mt][nt], af[mt], bf[nt]);
        }
    }

#pragma unroll
    for (int mt = 0; mt < 2; mt++) {
#pragma unroll
        for (int nt = 0; nt < 8; nt++) {
            int colN = bn + wn + nt * 8 + qid * 2;
            int row  = bm + wm + mt * 16 + grp;
            float2 bv = *(const float2*)(bias + colN);
            float2 v0, v1;
            v0.x = acc[mt][nt][0] + bv.x; v0.y = acc[mt][nt][1] + bv.y;
            v1.x = acc[mt][nt][2] + bv.x; v1.y = acc[mt][nt][3] + bv.y;
            if (do_relu) {
                v0.x = fmaxf(v0.x, 0.f); v0.y = fmaxf(v0.y, 0.f);
                v1.x = fmaxf(v1.x, 0.f); v1.y = fmaxf(v1.y, 0.f);
            }
            if (Cf) {
                *(float2*)(Cf + (size_t)row * ldc + colN)       = v0;
                *(float2*)(Cf + (size_t)(row + 8) * ldc + colN) = v1;
            }
            if (Ch) {
                *(__half2*)(Ch + (size_t)row * ldc + colN)       = __floats2half2_rn(v0.x, v0.y);
                *(__half2*)(Ch + (size_t)(row + 8) * ldc + colN) = __floats2half2_rn(v1.x, v1.y);
            }
        }
    }
}

// ---------------- fused GRU step (R6 shape + h-from-traj + h smem prefetch) -----
// CTA 128x96, 8 warps: wm=(warp&3)*32, wn=(warp>>2)*48.
// hsrc: fp32 hidden state, row stride hstride (latf0: 512, traj slice: 4096).
__global__ __launch_bounds__(THREADS, 2) void gemm_gru(
    const __half* __restrict__ A,
    const float* __restrict__ b_ih, const float* __restrict__ b_hh,
    const float* __restrict__ hsrc, int hstride,
    __half* __restrict__ lath_out,
    float* __restrict__ traj, int step)
{
    extern __shared__ __align__(16) char sm[];
    const uint32_t sbase = smem_u32(sm);

    const int tid  = threadIdx.x;
    const int warp = tid >> 5;
    const int lane = tid & 31;
    const int bm  = blockIdx.y * BM;
    const int blk = blockIdx.x;               // 16-dim block, 0..31
    const int wm = (warp & 3) * 32;
    const int wn = (warp >> 2) * 48;          // 0 or 48
    const int grp = lane >> 2;
    const int qid = lane & 3;
    const int arow = ((lane >> 3) & 1) * 8 + (lane & 7);
    const int acol = ((lane >> 4) & 1) * 8;
    const int brow = ((lane >> 4) & 1) * 8 + (lane & 7);
    const int bcol = ((lane >> 3) & 1) * 8;

    const __half* Bw = g_wgru + (size_t)blk * GBN * 512;

    float acc[2][6][4];
#pragma unroll
    for (int i = 0; i < 2; i++)
#pragma unroll
        for (int j = 0; j < 6; j++)
#pragma unroll
            for (int k = 0; k < 4; k++) acc[i][j][k] = 0.f;

    const int niter = 512 / BK;               // 8

    auto load_tile = [&](int it) {
        const int k0 = it * BK;
        const uint32_t sa = sbase + (uint32_t)(it % 3) * GSTG;
        const uint32_t sb = sa + BM * SROW;
#pragma unroll
        for (int t = tid; t < 1024; t += THREADS) {     // A: 128 rows x 8 chunks
            int r = t >> 3, c = t & 7;
            cp16(sa + r * SROW + c * 16, A + (size_t)(bm + r) * 512 + k0 + c * 8);
        }
#pragma unroll
        for (int t = tid; t < 768; t += THREADS) {      // B: 96 rows x 8 chunks
            int r = t >> 3, c = t & 7;
            cp16(sb + r * SROW + c * 16, Bw + (size_t)r * 512 + k0 + c * 8);
        }
        cp_commit();
    };

    // h prefetch: 128 rows x 16 f32 = 512 x 16B chunks, joins tile-0's group
    {
        const float* hbase = hsrc + blk * 16;
#pragma unroll
        for (int t = tid; t < 512; t += THREADS) {
            int r = t >> 2, c = t & 3;
            cp16(sbase + HOFF + r * 64 + c * 16,
                 hbase + (size_t)(bm + r) * hstride + c * 4);
        }
    }
    load_tile(0);      // commit includes h chunks
    load_tile(1);

    for (int it = 0; it < niter; it++) {
        if (it + 1 < niter) cp_wait<1>(); else cp_wait<0>();
        __syncthreads();
        if (it + 2 < niter) load_tile(it + 2);

        const uint32_t sa = sbase + (uint32_t)(it % 3) * GSTG;
        const uint32_t sb = sa + BM * SROW;

#pragma unroll
        for (int kk = 0; kk < BK; kk += 16) {
            uint32_t af[2][4], bf[6][2];
#pragma unroll
            for (int mt = 0; mt < 2; mt++)
                ldsm4(af[mt], sa + (wm + mt * 16 + arow) * SROW + (kk + acol) * 2);
#pragma unroll
            for (int np = 0; np < 3; np++) {
                uint32_t r[4];
                ldsm4(r, sb + (wn + np * 16 + brow) * SROW + (kk + bcol) * 2);
                bf[2 * np][0] = r[0]; bf[2 * np][1] = r[1];
                bf[2 * np + 1][0] = r[2]; bf[2 * np + 1][1] = r[3];
            }
#pragma unroll
            for (int mt = 0; mt < 2; mt++)
#pragma unroll
                for (int nt = 0; nt < 6; nt++)
                    mma16(acc[mt][nt], af[mt], bf[nt]);
        }
    }

    // ---- register-local GRU gate epilogue (h from smem) ----
    const int dloc = (wn / 48) * 8 + qid * 2;      // local dim 0..15
    const int c = blk * 16 + dloc;
    const float2 bir = *(const float2*)(b_ih + c);
    const float2 biz = *(const float2*)(b_ih + 512 + c);
    const float2 bin = *(const float2*)(b_ih + 1024 + c);
    const float2 bhr = *(const float2*)(b_hh + c);
    const float2 bhz = *(const float2*)(b_hh + 512 + c);
    const float2 bhn = *(const float2*)(b_hh + 1024 + c);

#pragma unroll
    for (int mt = 0; mt < 2; mt++) {
#pragma unroll
        for (int hv = 0; hv < 2; hv++) {
            const int rloc = wm + mt * 16 + grp + hv * 8;
            const int row = bm + rloc;
            const int k0 = hv * 2;
            const float2 hin = *(const float2*)(sm + HOFF + rloc * 64 + dloc * 4);

            float r0 = sigmf(acc[mt][0][k0]     + bir.x + acc[mt][3][k0]     + bhr.x);
            float r1 = sigmf(acc[mt][0][k0 + 1] + bir.y + acc[mt][3][k0 + 1] + bhr.y);
            float z0 = sigmf(acc[mt][1][k0]     + biz.x + acc[mt][4][k0]     + bhz.x);
            float z1 = sigmf(acc[mt][1][k0 + 1] + biz.y + acc[mt][4][k0 + 1] + bhz.y);
            float n0 = tanhf(acc[mt][2][k0]     + bin.x + r0 * (acc[mt][5][k0]     + bhn.x));
            float n1 = tanhf(acc[mt][2][k0 + 1] + bin.y + r1 * (acc[mt][5][k0 + 1] + bhn.y));
            float o0 = (1.f - z0) * n0 + z0 * hin.x;
            float o1 = (1.f - z1) * n1 + z1 * hin.y;

            *(__half2*)(lath_out + (size_t)row * 512 + c) = __floats2half2_rn(o0, o1);
            *(float2*)(traj + (size_t)row * 4096 + step * 512 + c) = make_float2(o0, o1);
        }
    }
}

// ---------------- mega prep kernel (single launch) ------------------------------
#define PQ_X    4194304                 // 8192*2048/4
#define PQ_E1   (PQ_X + 524288)
#define PQ_E2   (PQ_E1 + 131072)
#define PQ_D1   (PQ_E2 + 131072)
#define PQ_D2   (PQ_D1 + 524288)
#define PQ_GRU  (PQ_D2 + 393216)
__global__ __launch_bounds__(256) void prep(
    const float* __restrict__ x,
    const float* __restrict__ We1, const float* __restrict__ We2,
    const float* __restrict__ Wd1, const float* __restrict__ Wd2,
    const float* __restrict__ w_ih, const float* __restrict__ w_hh)
{
    int i = blockIdx.x * blockDim.x + threadIdx.x;
    if (i >= PQ_GRU) return;
    const float4* src;
    __half2* dst;
    if (i < PQ_X) {
        src = (const float4*)x + i;
        dst = (__half2*)g_xh + 2 * (size_t)i;
    } else if (i < PQ_E1) {
        int j = i - PQ_X;
        src = (const float4*)We1 + j;
        dst = (__half2*)(g_wh + OFF_ENC1) + 2 * (size_t)j;
    } else if (i < PQ_E2) {
        int j = i - PQ_E1;
        src = (const float4*)We2 + j;
        dst = (__half2*)(g_wh + OFF_ENC2) + 2 * (size_t)j;
    } else if (i < PQ_D1) {
        int j = i - PQ_E2;
        src = (const float4*)Wd1 + j;
        dst = (__half2*)(g_wh + OFF_DEC1) + 2 * (size_t)j;
    } else if (i < PQ_D2) {
        int j = i - PQ_D1;
        src = (const float4*)Wd2 + j;
        dst = (__half2*)(g_wh + OFF_DEC2) + 2 * (size_t)j;
    } else {
        int j = i - PQ_D2;                 // gru reorder: 3072 rows x 128 quads
        int o = j >> 7, q = j & 127;
        int d48 = o / 48, rem = o % 48, g = rem >> 3, e = rem & 7;
        int cc = d48 * 8 + e;
        const float* s = (g < 3) ? (w_ih + (size_t)(g * 512 + cc) * 512)
                                 : (w_hh + (size_t)((g - 3) * 512 + cc) * 512);
        src = (const float4*)s + q;
        dst = (__half2*)(g_wgru + (size_t)o * 512) + 2 * q;
    }
    float4 v = *src;
    dst[0] = __floats2half2_rn(v.x, v.y);
    dst[1] = __floats2half2_rn(v.z, v.w);
}

// ---------------- launch ---------------------------------------------------------
extern "C" void kernel_launch(void* const* d_in, const int* in_sizes, int n_in,
                              void* d_out, int out_size)
{
    const int bse = (n_in >= 14) ? 2 : 1;
    const float* x      = (const float*)d_in[0];
    const float* W_enc1 = (const float*)d_in[bse + 0];
    const float* b_enc1 = (const float*)d_in[bse + 1];
    const float* W_enc2 = (const float*)d_in[bse + 2];
    const float* b_enc2 = (const float*)d_in[bse + 3];
    const float* W_dec1 = (const float*)d_in[bse + 4];
    const float* b_dec1 = (const float*)d_in[bse + 5];
    const float* W_dec2 = (const float*)d_in[bse + 6];
    const float* b_dec2 = (const float*)d_in[bse + 7];
    const float* w_ih   = (const float*)d_in[bse + 8];
    const float* w_hh   = (const float*)d_in[bse + 9];
    const float* b_ih   = (const float*)d_in[bse + 10];
    const float* b_hh   = (const float*)d_in[bse + 11];

    float* decoded = (float*)d_out;
    float* traj    = decoded + (size_t)MROWS * 2048;

    __half *xh, *h1h, *wh;
    __half *lath[2];
    float *latf0;
    cudaGetSymbolAddress((void**)&xh,    g_xh);
    cudaGetSymbolAddress((void**)&h1h,   g_h1h);
    cudaGetSymbolAddress((void**)&wh,    g_wh);
    cudaGetSymbolAddress((void**)&latf0, g_latf0);
    {   __half* p; cudaGetSymbolAddress((void**)&p, g_lath);
        lath[0] = p; lath[1] = p + (size_t)MROWS * 512; }

    cudaFuncSetAttribute(gemm_f16, cudaFuncAttributeMaxDynamicSharedMemorySize, SMEM_MAIN);
    cudaFuncSetAttribute(gemm_gru, cudaFuncAttributeMaxDynamicSharedMemorySize, SMEM_GRU);

    const dim3 blk(THREADS);
    const int gy = MROWS / BM;  // 64

    // launch 0: all prep work in one kernel
    prep<<<(PQ_GRU + 255) / 256, 256>>>(x, W_enc1, W_enc2, W_dec1, W_dec2,
                                        w_ih, w_hh);

    // launches 1,2: encode
    gemm_f16<<<dim3(1024 / BN, gy), blk, SMEM_MAIN>>>(
        xh, 2048, wh + OFF_ENC1, 2048, b_enc1, nullptr, h1h, 1024, 2048, 1);
    gemm_f16<<<dim3(512 / BN, gy), blk, SMEM_MAIN>>>(
        h1h, 1024, wh + OFF_ENC2, 1024, b_enc2, latf0, lath[0], 512, 1024, 0);

    // launches 3..10: 8 fused GRU steps (launch #5 = step 2, for ncu -s 5)
    for (int step = 0; step < 8; step++) {
        int s = step & 1, t = s ^ 1;
        const float* hsrc = (step == 0) ? latf0 : (traj + (size_t)(step - 1) * 512);
        int hstride = (step == 0) ? 512 : 4096;
        gemm_gru<<<dim3(32, gy), blk, SMEM_GRU>>>(
            lath[s], b_ih, b_hh, hsrc, hstride, lath[t], traj, step);
    }

    // launches 11,12: decode (after 8 steps latent is back in lath[0])
    gemm_f16<<<dim3(1024 / BN, gy), blk, SMEM_MAIN>>>(
        lath[0], 512, wh + OFF_DEC1, 512, b_dec1, nullptr, h1h, 1024, 512, 1);
    gemm_f16<<<dim3(2048 / BN, gy), blk, SMEM_MAIN>>>(
        h1h, 1024, wh + OFF_DEC2, 1024, b_dec2, decoded, nullptr, 2048, 1024, 0);
}

// round 10
// speedup vs baseline: 1.4821x; 1.1567x over previous
#include <cuda_runtime.h>
#include <cuda_fp16.h>
#include <cstdint>

// ----------------------------------------------------------------------------
// LatentReasoningModule, sm_100 legacy tensor-core path.
//   fp16 mma.m16n8k16 (fp32 accum), ldmatrix, 3-stage cp.async, 1 sync/k-tile.
//   encode: H(2048)->2L(1024) relu ->L(512)
//   8x GRU(512): fused GEMM+gate kernel. R10: exploit x==h in GRUCell(lat,lat)
//     -> r,z gates use combined weights (W_i*+W_h*), GEMM N: 3072 -> 2048
//     (33% fewer flops). Gate layout per 8 dims: [rz_r, rz_z, i_n, h_n].
//     CTA 128x64, warp tile 32x32, 2 CTAs/SM, h prefetched to smem.
//   decode: L->2L relu ->H
// ----------------------------------------------------------------------------

#define MROWS 8192
#define THREADS 256
#define SROW 144                    // bytes per smem row: 64 halves + 8 pad

// ---- main GEMM tile (encode/decode): 3-stage ----
#define BM 128
#define BN 128
#define BK 64
#define AB_BYTES   (BM * SROW)          // 18432
#define STG_BYTES  (2 * AB_BYTES)       // 36864
#define SMEM_MAIN  (3 * STG_BYTES)      // 110592

// ---- GRU GEMM tile: CTA 128x64, warp tile 32x32, 3-stage + h tile ----
#define GBN 64
#define GSTG ((BM + GBN) * SROW)        // 27648
#define HOFF (3 * GSTG)                 // 82944: h tile (128 rows x 16 f32)
#define SMEM_GRU (HOFF + BM * 64)       // 91136 (x2 CTAs = 182 KB/SM)

// ---------------- scratch (device globals) ------------------------------------
__device__ __half g_xh[(size_t)MROWS * 2048];
__device__ __half g_h1h[(size_t)MROWS * 1024];
__device__ __half g_lath[2][(size_t)MROWS * 512];
__device__ float  g_latf0[(size_t)MROWS * 512];   // encoder latent (h for step 0)
#define OFF_ENC1  0
#define OFF_ENC2  2097152
#define OFF_DEC1  2621440
#define OFF_DEC2  3145728
__device__ __half g_wh[5242880];
__device__ __half g_wgru[2048 * 512];   // combined gate-grouped GRU weights
__device__ float  g_bg[2048];           // [b_r | b_z | b_in | b_hn] by dim

// ---------------- helpers -----------------------------------------------------
__device__ __forceinline__ uint32_t smem_u32(const void* p) {
    uint32_t a;
    asm("{ .reg .u64 t; cvta.to.shared.u64 t, %1; cvt.u32.u64 %0, t; }"
        : "=r"(a) : "l"(p));
    return a;
}
__device__ __forceinline__ void cp16(uint32_t dst, const void* src) {
    asm volatile("cp.async.cg.shared.global [%0], [%1], 16;"
                 :: "r"(dst), "l"(src));
}
__device__ __forceinline__ void cp_commit() {
    asm volatile("cp.async.commit_group;" ::: "memory");
}
template <int N>
__device__ __forceinline__ void cp_wait() {
    asm volatile("cp.async.wait_group %0;" :: "n"(N) : "memory");
}
__device__ __forceinline__ void ldsm4(uint32_t* r, uint32_t addr) {
    asm volatile("ldmatrix.sync.aligned.m8n8.x4.shared.b16 {%0,%1,%2,%3}, [%4];"
                 : "=r"(r[0]), "=r"(r[1]), "=r"(r[2]), "=r"(r[3]) : "r"(addr));
}
__device__ __forceinline__ void mma16(float* c, const uint32_t* a, const uint32_t* b) {
    asm volatile(
        "mma.sync.aligned.m16n8k16.row.col.f32.f16.f16.f32 "
        "{%0,%1,%2,%3},{%4,%5,%6,%7},{%8,%9},{%0,%1,%2,%3};"
        : "+f"(c[0]), "+f"(c[1]), "+f"(c[2]), "+f"(c[3])
        : "r"(a[0]), "r"(a[1]), "r"(a[2]), "r"(a[3]), "r"(b[0]), "r"(b[1]));
}
__device__ __forceinline__ float sigmf(float x) {
    return 1.f / (1.f + __expf(-x));
}

// ---------------- main fp16 GEMM (encode/decode) -------------------------------
__global__ __launch_bounds__(THREADS, 2) void gemm_f16(
    const __half* __restrict__ A, int lda,
    const __half* __restrict__ B, int ldb,
    const float* __restrict__ bias,
    float* __restrict__ Cf, __half* __restrict__ Ch, int ldc,
    int K, int do_relu)
{
    extern __shared__ __align__(16) char sm[];
    const uint32_t sbase = smem_u32(sm);

    const int tid  = threadIdx.x;
    const int warp = tid >> 5;
    const int lane = tid & 31;
    const int bm = blockIdx.y * BM;
    const int bn = blockIdx.x * BN;
    const int wm = (warp & 3) * 32;
    const int wn = (warp >> 2) * 64;
    const int grp = lane >> 2;
    const int qid = lane & 3;
    const int arow = ((lane >> 3) & 1) * 8 + (lane & 7);
    const int acol = ((lane >> 4) & 1) * 8;
    const int brow = ((lane >> 4) & 1) * 8 + (lane & 7);
    const int bcol = ((lane >> 3) & 1) * 8;

    float acc[2][8][4];
#pragma unroll
    for (int i = 0; i < 2; i++)
#pragma unroll
        for (int j = 0; j < 8; j++)
#pragma unroll
            for (int k = 0; k < 4; k++) acc[i][j][k] = 0.f;

    const int niter = K / BK;

    auto load_tile = [&](int it) {
        const int k0 = it * BK;
        const uint32_t sa = sbase + (uint32_t)(it % 3) * STG_BYTES;
        const uint32_t sb = sa + AB_BYTES;
#pragma unroll
        for (int t = tid; t < 1024; t += THREADS) {
            int r = t >> 3, c = t & 7;
            cp16(sa + r * SROW + c * 16, A + (size_t)(bm + r) * lda + k0 + c * 8);
        }
#pragma unroll
        for (int t = tid; t < 1024; t += THREADS) {
            int r = t >> 3, c = t & 7;
            cp16(sb + r * SROW + c * 16, B + (size_t)(bn + r) * ldb + k0 + c * 8);
        }
        cp_commit();
    };

    load_tile(0);
    load_tile(1);

    for (int it = 0; it < niter; it++) {
        if (it + 1 < niter) cp_wait<1>(); else cp_wait<0>();
        __syncthreads();
        if (it + 2 < niter) load_tile(it + 2);

        const uint32_t sa = sbase + (uint32_t)(it % 3) * STG_BYTES;
        const uint32_t sb = sa + AB_BYTES;

#pragma unroll
        for (int kk = 0; kk < BK; kk += 16) {
            uint32_t af[2][4], bf[8][2];
#pragma unroll
            for (int mt = 0; mt < 2; mt++)
                ldsm4(af[mt], sa + (wm + mt * 16 + arow) * SROW + (kk + acol) * 2);
#pragma unroll
            for (int np = 0; np < 4; np++) {
                uint32_t r[4];
                ldsm4(r, sb + (wn + np * 16 + brow) * SROW + (kk + bcol) * 2);
                bf[2 * np][0] = r[0]; bf[2 * np][1] = r[1];
                bf[2 * np + 1][0] = r[2]; bf[2 * np + 1][1] = r[3];
            }
#pragma unroll
            for (int mt = 0; mt < 2; mt++)
#pragma unroll
                for (int nt = 0; nt < 8; nt++)
                    mma16(acc[mt][nt], af[mt], bf[nt]);
        }
    }

#pragma unroll
    for (int mt = 0; mt < 2; mt++) {
#pragma unroll
        for (int nt = 0; nt < 8; nt++) {
            int colN = bn + wn + nt * 8 + qid * 2;
            int row  = bm + wm + mt * 16 + grp;
            float2 bv = *(const float2*)(bias + colN);
            float2 v0, v1;
            v0.x = acc[mt][nt][0] + bv.x; v0.y = acc[mt][nt][1] + bv.y;
            v1.x = acc[mt][nt][2] + bv.x; v1.y = acc[mt][nt][3] + bv.y;
            if (do_relu) {
                v0.x = fmaxf(v0.x, 0.f); v0.y = fmaxf(v0.y, 0.f);
                v1.x = fmaxf(v1.x, 0.f); v1.y = fmaxf(v1.y, 0.f);
            }
            if (Cf) {
                *(float2*)(Cf + (size_t)row * ldc + colN)       = v0;
                *(float2*)(Cf + (size_t)(row + 8) * ldc + colN) = v1;
            }
            if (Ch) {
                *(__half2*)(Ch + (size_t)row * ldc + colN)       = __floats2half2_rn(v0.x, v0.y);
                *(__half2*)(Ch + (size_t)(row + 8) * ldc + colN) = __floats2half2_rn(v1.x, v1.y);
            }
        }
    }
}

// ---------------- fused GRU step (R10: combined r/z weights, N=2048) ------------
// g_wgru row o: grp8 = o/32, g = (o%32)/8, e = o%8; dim c = grp8*8 + e.
//   g=0: W_ir+W_hr row c; g=1: W_iz+W_hz row c; g=2: W_in row c; g=3: W_hn row c.
// CTA 128x64 (2 x 32-col gate groups = 16 dims), 8 warps: wm=(warp&3)*32,
// wn=(warp>>2)*32. Each thread owns all 4 gate pre-acts for dims qid*2, qid*2+1.
__global__ __launch_bounds__(THREADS, 2) void gemm_gru(
    const __half* __restrict__ A,
    const float* __restrict__ hsrc, int hstride,
    __half* __restrict__ lath_out,
    float* __restrict__ traj, int step)
{
    extern __shared__ __align__(16) char sm[];
    const uint32_t sbase = smem_u32(sm);

    const int tid  = threadIdx.x;
    const int warp = tid >> 5;
    const int lane = tid & 31;
    const int bm  = blockIdx.y * BM;
    const int blk = blockIdx.x;               // 16-dim block, 0..31
    const int wm = (warp & 3) * 32;
    const int wn = (warp >> 2) * 32;          // 0 or 32
    const int grp = lane >> 2;
    const int qid = lane & 3;
    const int arow = ((lane >> 3) & 1) * 8 + (lane & 7);
    const int acol = ((lane >> 4) & 1) * 8;
    const int brow = ((lane >> 4) & 1) * 8 + (lane & 7);
    const int bcol = ((lane >> 3) & 1) * 8;

    const __half* Bw = g_wgru + (size_t)blk * GBN * 512;

    float acc[2][4][4];
#pragma unroll
    for (int i = 0; i < 2; i++)
#pragma unroll
        for (int j = 0; j < 4; j++)
#pragma unroll
            for (int k = 0; k < 4; k++) acc[i][j][k] = 0.f;

    const int niter = 512 / BK;               // 8

    auto load_tile = [&](int it) {
        const int k0 = it * BK;
        const uint32_t sa = sbase + (uint32_t)(it % 3) * GSTG;
        const uint32_t sb = sa + BM * SROW;
#pragma unroll
        for (int t = tid; t < 1024; t += THREADS) {     // A: 128 rows x 8 chunks
            int r = t >> 3, c = t & 7;
            cp16(sa + r * SROW + c * 16, A + (size_t)(bm + r) * 512 + k0 + c * 8);
        }
#pragma unroll
        for (int t = tid; t < 512; t += THREADS) {      // B: 64 rows x 8 chunks
            int r = t >> 3, c = t & 7;
            cp16(sb + r * SROW + c * 16, Bw + (size_t)r * 512 + k0 + c * 8);
        }
        cp_commit();
    };

    // h prefetch: 128 rows x 16 f32 = 512 x 16B chunks, joins tile-0's group
    {
        const float* hbase = hsrc + blk * 16;
#pragma unroll
        for (int t = tid; t < 512; t += THREADS) {
            int r = t >> 2, c = t & 3;
            cp16(sbase + HOFF + r * 64 + c * 16,
                 hbase + (size_t)(bm + r) * hstride + c * 4);
        }
    }
    load_tile(0);      // commit includes h chunks
    load_tile(1);

    for (int it = 0; it < niter; it++) {
        if (it + 1 < niter) cp_wait<1>(); else cp_wait<0>();
        __syncthreads();
        if (it + 2 < niter) load_tile(it + 2);

        const uint32_t sa = sbase + (uint32_t)(it % 3) * GSTG;
        const uint32_t sb = sa + BM * SROW;

#pragma unroll
        for (int kk = 0; kk < BK; kk += 16) {
            uint32_t af[2][4], bf[4][2];
#pragma unroll
            for (int mt = 0; mt < 2; mt++)
                ldsm4(af[mt], sa + (wm + mt * 16 + arow) * SROW + (kk + acol) * 2);
#pragma unroll
            for (int np = 0; np < 2; np++) {
                uint32_t r[4];
                ldsm4(r, sb + (wn + np * 16 + brow) * SROW + (kk + bcol) * 2);
                bf[2 * np][0] = r[0]; bf[2 * np][1] = r[1];
                bf[2 * np + 1][0] = r[2]; bf[2 * np + 1][1] = r[3];
            }
#pragma unroll
            for (int mt = 0; mt < 2; mt++)
#pragma unroll
                for (int nt = 0; nt < 4; nt++)
                    mma16(acc[mt][nt], af[mt], bf[nt]);
        }
    }

    // ---- register-local GRU gate epilogue (h from smem) ----
    // acc[mt][0]=rz_r, [1]=rz_z, [2]=i_n, [3]=h_n for dims qid*2, qid*2+1
    const int dloc = (wn >> 2) + qid * 2;          // (warp>>2)*8 + qid*2, 0..15
    const int c = blk * 16 + dloc;
    const float2 brv = *(const float2*)(g_bg + c);
    const float2 bzv = *(const float2*)(g_bg + 512 + c);
    const float2 bin = *(const float2*)(g_bg + 1024 + c);
    const float2 bhn = *(const float2*)(g_bg + 1536 + c);

#pragma unroll
    for (int mt = 0; mt < 2; mt++) {
#pragma unroll
        for (int hv = 0; hv < 2; hv++) {
            const int rloc = wm + mt * 16 + grp + hv * 8;
            const int row = bm + rloc;
            const int k0 = hv * 2;
            const float2 hin = *(const float2*)(sm + HOFF + rloc * 64 + dloc * 4);

            float r0 = sigmf(acc[mt][0][k0]     + brv.x);
            float r1 = sigmf(acc[mt][0][k0 + 1] + brv.y);
            float z0 = sigmf(acc[mt][1][k0]     + bzv.x);
            float z1 = sigmf(acc[mt][1][k0 + 1] + bzv.y);
            float n0 = tanhf(acc[mt][2][k0]     + bin.x + r0 * (acc[mt][3][k0]     + bhn.x));
            float n1 = tanhf(acc[mt][2][k0 + 1] + bin.y + r1 * (acc[mt][3][k0 + 1] + bhn.y));
            float o0 = (1.f - z0) * n0 + z0 * hin.x;
            float o1 = (1.f - z1) * n1 + z1 * hin.y;

            *(__half2*)(lath_out + (size_t)row * 512 + c) = __floats2half2_rn(o0, o1);
            *(float2*)(traj + (size_t)row * 4096 + step * 512 + c) = make_float2(o0, o1);
        }
    }
}

// ---------------- mega prep kernel (single launch) ------------------------------
#define PQ_X    4194304                 // 8192*2048/4
#define PQ_E1   (PQ_X + 524288)
#define PQ_E2   (PQ_E1 + 131072)
#define PQ_D1   (PQ_E2 + 131072)
#define PQ_D2   (PQ_D1 + 524288)
#define PQ_GW   (PQ_D2 + 262144)        // +2048 rows x 128 quads
#define PQ_ALL  (PQ_GW + 512)           // +bias quads
__global__ __launch_bounds__(256) void prep(
    const float* __restrict__ x,
    const float* __restrict__ We1, const float* __restrict__ We2,
    const float* __restrict__ Wd1, const float* __restrict__ Wd2,
    const float* __restrict__ w_ih, const float* __restrict__ w_hh,
    const float* __restrict__ b_ih, const float* __restrict__ b_hh)
{
    int i = blockIdx.x * blockDim.x + threadIdx.x;
    if (i >= PQ_ALL) return;
    if (i >= PQ_GW) {
        // combined biases: g_bg = [b_r | b_z | b_in | b_hn] indexed by dim
        int j = i - PQ_GW;             // 0..511
        int g = j >> 7, q = j & 127;
        int c = q * 4;
        float4 v;
        if (g == 0) {
            float4 a = *(const float4*)(b_ih + c), b = *(const float4*)(b_hh + c);
            v = make_float4(a.x + b.x, a.y + b.y, a.z + b.z, a.w + b.w);
        } else if (g == 1) {
            float4 a = *(const float4*)(b_ih + 512 + c), b = *(const float4*)(b_hh + 512 + c);
            v = make_float4(a.x + b.x, a.y + b.y, a.z + b.z, a.w + b.w);
        } else if (g == 2) {
            v = *(const float4*)(b_ih + 1024 + c);
        } else {
            v = *(const float4*)(b_hh + 1024 + c);
        }
        *(float4*)(g_bg + g * 512 + c) = v;
        return;
    }
    const float4* src;
    __half2* dst;
    if (i < PQ_X) {
        src = (const float4*)x + i;
        dst = (__half2*)g_xh + 2 * (size_t)i;
    } else if (i < PQ_E1) {
        int j = i - PQ_X;
        src = (const float4*)We1 + j;
        dst = (__half2*)(g_wh + OFF_ENC1) + 2 * (size_t)j;
    } else if (i < PQ_E2) {
        int j = i - PQ_E1;
        src = (const float4*)We2 + j;
        dst = (__half2*)(g_wh + OFF_ENC2) + 2 * (size_t)j;
    } else if (i < PQ_D1) {
        int j = i - PQ_E2;
        src = (const float4*)Wd1 + j;
        dst = (__half2*)(g_wh + OFF_DEC1) + 2 * (size_t)j;
    } else if (i < PQ_D2) {
        int j = i - PQ_D1;
        src = (const float4*)Wd2 + j;
        dst = (__half2*)(g_wh + OFF_DEC2) + 2 * (size_t)j;
    } else {
        // combined GRU weights: row o: grp8=o/32, g=(o%32)/8, e=o%8, c=grp8*8+e
        int j = i - PQ_D2;             // 2048 rows x 128 quads
        int o = j >> 7, q = j & 127;
        int grp8 = o >> 5, g = (o >> 3) & 3, e = o & 7;
        int cc = grp8 * 8 + e;
        float4 v;
        if (g == 0) {
            float4 a = ((const float4*)(w_ih + (size_t)cc * 512))[q];
            float4 b = ((const float4*)(w_hh + (size_t)cc * 512))[q];
            v = make_float4(a.x + b.x, a.y + b.y, a.z + b.z, a.w + b.w);
        } else if (g == 1) {
            float4 a = ((const float4*)(w_ih + (size_t)(512 + cc) * 512))[q];
            float4 b = ((const float4*)(w_hh + (size_t)(512 + cc) * 512))[q];
            v = make_float4(a.x + b.x, a.y + b.y, a.z + b.z, a.w + b.w);
        } else if (g == 2) {
            v = ((const float4*)(w_ih + (size_t)(1024 + cc) * 512))[q];
        } else {
            v = ((const float4*)(w_hh + (size_t)(1024 + cc) * 512))[q];
        }
        __half2* d = (__half2*)(g_wgru + (size_t)o * 512) + 2 * q;
        d[0] = __floats2half2_rn(v.x, v.y);
        d[1] = __floats2half2_rn(v.z, v.w);
        return;
    }
    float4 v = *src;
    dst[0] = __floats2half2_rn(v.x, v.y);
    dst[1] = __floats2half2_rn(v.z, v.w);
}

// ---------------- launch ---------------------------------------------------------
extern "C" void kernel_launch(void* const* d_in, const int* in_sizes, int n_in,
                              void* d_out, int out_size)
{
    const int bse = (n_in >= 14) ? 2 : 1;
    const float* x      = (const float*)d_in[0];
    const float* W_enc1 = (const float*)d_in[bse + 0];
    const float* b_enc1 = (const float*)d_in[bse + 1];
    const float* W_enc2 = (const float*)d_in[bse + 2];
    const float* b_enc2 = (const float*)d_in[bse + 3];
    const float* W_dec1 = (const float*)d_in[bse + 4];
    const float* b_dec1 = (const float*)d_in[bse + 5];
    const float* W_dec2 = (const float*)d_in[bse + 6];
    const float* b_dec2 = (const float*)d_in[bse + 7];
    const float* w_ih   = (const float*)d_in[bse + 8];
    const float* w_hh   = (const float*)d_in[bse + 9];
    const float* b_ih   = (const float*)d_in[bse + 10];
    const float* b_hh   = (const float*)d_in[bse + 11];

    float* decoded = (float*)d_out;
    float* traj    = decoded + (size_t)MROWS * 2048;

    __half *xh, *h1h, *wh;
    __half *lath[2];
    float *latf0;
    cudaGetSymbolAddress((void**)&xh,    g_xh);
    cudaGetSymbolAddress((void**)&h1h,   g_h1h);
    cudaGetSymbolAddress((void**)&wh,    g_wh);
    cudaGetSymbolAddress((void**)&latf0, g_latf0);
    {   __half* p; cudaGetSymbolAddress((void**)&p, g_lath);
        lath[0] = p; lath[1] = p + (size_t)MROWS * 512; }

    cudaFuncSetAttribute(gemm_f16, cudaFuncAttributeMaxDynamicSharedMemorySize, SMEM_MAIN);
    cudaFuncSetAttribute(gemm_gru, cudaFuncAttributeMaxDynamicSharedMemorySize, SMEM_GRU);

    const dim3 blk(THREADS);
    const int gy = MROWS / BM;  // 64

    // launch 0: all prep work in one kernel
    prep<<<(PQ_ALL + 255) / 256, 256>>>(x, W_enc1, W_enc2, W_dec1, W_dec2,
                                        w_ih, w_hh, b_ih, b_hh);

    // launches 1,2: encode
    gemm_f16<<<dim3(1024 / BN, gy), blk, SMEM_MAIN>>>(
        xh, 2048, wh + OFF_ENC1, 2048, b_enc1, nullptr, h1h, 1024, 2048, 1);
    gemm_f16<<<dim3(512 / BN, gy), blk, SMEM_MAIN>>>(
        h1h, 1024, wh + OFF_ENC2, 1024, b_enc2, latf0, lath[0], 512, 1024, 0);

    // launches 3..10: 8 fused GRU steps (launch #5 = step 2, for ncu -s 5)
    for (int step = 0; step < 8; step++) {
        int s = step & 1, t = s ^ 1;
        const float* hsrc = (step == 0) ? latf0 : (traj + (size_t)(step - 1) * 512);
        int hstride = (step == 0) ? 512 : 4096;
        gemm_gru<<<dim3(32, gy), blk, SMEM_GRU>>>(
            lath[s], hsrc, hstride, lath[t], traj, step);
    }

    // launches 11,12: decode (after 8 steps latent is back in lath[0])
    gemm_f16<<<dim3(1024 / BN, gy), blk, SMEM_MAIN>>>(
        lath[0], 512, wh + OFF_DEC1, 512, b_dec1, nullptr, h1h, 1024, 512, 1);
    gemm_f16<<<dim3(2048 / BN, gy), blk, SMEM_MAIN>>>(
        h1h, 1024, wh + OFF_DEC2, 1024, b_dec2, decoded, nullptr, 2048, 1024, 0);
}